// round 14
// baseline (speedup 1.0000x reference)
#include <cuda_runtime.h>
#include <cuda_bf16.h>
#include <math.h>
#include <stdint.h>

// ---------------------------------------------------------------------------
// Problem constants
// ---------------------------------------------------------------------------
#define MAXN 125000
#define MAXE 500000

// Scratch (device globals -- no allocation allowed)
__device__ float g_hsum  [(size_t)MAXN * 256];   // [N, H+X] segment sum
__device__ float g_gates [(size_t)MAXN * 512];   // activated gates f,i,u,o each [N,128]
__device__ float g_csum  [(size_t)MAXN * 128];   // segment_sum(c_src)  [N, H]
__device__ float g_bias  [512];                  // bW* + b*
__device__ uint32_t g_Bh2[128 * 512];            // gate W hi: bf16x2 pairs along K  [k2][j]
__device__ uint32_t g_Bl2[128 * 512];            // gate W lo
__device__ uint32_t g_Welh2[32 * 128];           // W_el hi: bf16x2 pairs along g  [g2][c]
__device__ uint32_t g_Well2[32 * 128];           // W_el lo
__device__ int   g_idx64;

// ---------------------------------------------------------------------------
// Helpers
// ---------------------------------------------------------------------------
__device__ __forceinline__ uint32_t packbf2(float x, float y)
{
    __nv_bfloat162 p = __floats2bfloat162_rn(x, y);
    return *(uint32_t*)&p;
}

__device__ __forceinline__ void split_pair(float x, float y, uint32_t& hi, uint32_t& lo)
{
    __nv_bfloat16 hx = __float2bfloat16(x);
    __nv_bfloat16 hy = __float2bfloat16(y);
    __nv_bfloat162 hp; hp.x = hx; hp.y = hy;
    hi = *(uint32_t*)&hp;
    lo = packbf2(x - __bfloat162float(hx), y - __bfloat162float(hy));
}

__device__ __forceinline__ void mma16816(float* d, const uint32_t* a, const uint32_t* b)
{
    asm volatile(
        "mma.sync.aligned.m16n8k16.row.col.f32.bf16.bf16.f32 "
        "{%0,%1,%2,%3}, {%4,%5,%6,%7}, {%8,%9}, {%0,%1,%2,%3};"
        : "+f"(d[0]), "+f"(d[1]), "+f"(d[2]), "+f"(d[3])
        : "r"(a[0]), "r"(a[1]), "r"(a[2]), "r"(a[3]), "r"(b[0]), "r"(b[1]));
}

__device__ __forceinline__ void red4(float* addr, float a, float b, float c, float d)
{
    asm volatile("red.global.add.v4.f32 [%0], {%1, %2, %3, %4};"
                 :: "l"(addr), "f"(a), "f"(b), "f"(c), "f"(d) : "memory");
}
__device__ __forceinline__ void red2(float* addr, float a, float b)
{
    asm volatile("red.global.add.v2.f32 [%0], {%1, %2};"
                 :: "l"(addr), "f"(a), "f"(b) : "memory");
}

__device__ __forceinline__ uint32_t smem_u32(const void* p)
{
    uint32_t a;
    asm("{ .reg .u64 t; cvta.to.shared.u64 t, %1; cvt.u32.u64 %0, t; }" : "=r"(a) : "l"(p));
    return a;
}
__device__ __forceinline__ void cp_async16(void* smem, const void* gmem)
{
    asm volatile("cp.async.cg.shared.global [%0], [%1], 16;"
                 :: "r"(smem_u32(smem)), "l"(gmem) : "memory");
}
#define CP_COMMIT()  asm volatile("cp.async.commit_group;" ::: "memory")
#define CP_WAIT0()   asm volatile("cp.async.wait_group 0;" ::: "memory")

__device__ __forceinline__ long long load_idx(const void* p, int i, int is64)
{
    return is64 ? ((const long long*)p)[i] : (long long)((const int*)p)[i];
}

// ---------------------------------------------------------------------------
// Merged setup kernel: packB + W_el pairs + biases + index-dtype detect.
// ---------------------------------------------------------------------------
__global__ void k_setup(const float* __restrict__ Wf, const float* __restrict__ Wi,
                        const float* __restrict__ Wu, const float* __restrict__ Wo,
                        const float* __restrict__ bWf, const float* __restrict__ bf,
                        const float* __restrict__ bWi, const float* __restrict__ bi,
                        const float* __restrict__ bWu, const float* __restrict__ bu,
                        const float* __restrict__ bWo, const float* __restrict__ bo,
                        const float* __restrict__ W_el,
                        const unsigned int* __restrict__ dwords)
{
    int id = blockIdx.x * blockDim.x + threadIdx.x;
    if (id < 65536) {                       // gate weights
        int k2 = id >> 9;
        int j  = id & 511;
        int q = j >> 7, jj = j & 127;
        const float* W = (q == 0) ? Wf : (q == 1) ? Wi : (q == 2) ? Wu : Wo;
        float w0 = W[jj * 256 + 2 * k2];
        float w1 = W[jj * 256 + 2 * k2 + 1];
        uint32_t hi, lo;
        split_pair(w0, w1, hi, lo);
        g_Bh2[id] = hi;
        g_Bl2[id] = lo;
    } else if (id < 65536 + 4096) {         // W_el pairs
        int t = id - 65536;
        int g2 = t >> 7, c = t & 127;
        float w0 = W_el[c * 64 + 2 * g2];
        float w1 = W_el[c * 64 + 2 * g2 + 1];
        uint32_t hi, lo;
        split_pair(w0, w1, hi, lo);
        g_Welh2[t] = hi;
        g_Well2[t] = lo;
    } else if (id < 69632 + 512) {          // biases
        int t = id - 69632;
        int q = t >> 7, j = t & 127;
        const float* bW = (q == 0) ? bWf : (q == 1) ? bWi : (q == 2) ? bWu : bWo;
        const float* bb = (q == 0) ? bf  : (q == 1) ? bi  : (q == 2) ? bu  : bo;
        g_bias[t] = bW[j] + bb[j];
    } else if (id == 70144) {               // index dtype probe
        int all_hi_zero = 1;
        for (int k = 0; k < 64; ++k)
            if (dwords[2 * k + 1] != 0u) { all_hi_zero = 0; break; }
        g_idx64 = all_hi_zero;
    }
}

// ---------------------------------------------------------------------------
// Edge-message GEMM (mma.sync bf16 3-term) + scatter.  (R8/R12-exact)
// ---------------------------------------------------------------------------
struct EdgeSm {
    uint32_t Ah[32 * 132];
    uint32_t Al[32 * 132];
    uint32_t Bh[32 * 132];
    uint32_t Bl[32 * 132];
    int   sdst[128];
    int   stype[128];
    float sWeoh[192];
    float sbeoh[64];
    float sbel[128];
};

__global__ __launch_bounds__(256, 2) void k_edgemm(
    const float* __restrict__ h_src, const float* __restrict__ embed,
    const float* __restrict__ c_src,
    const float* __restrict__ sfeat, const float* __restrict__ dfeat,
    const float* __restrict__ W_eoh, const float* __restrict__ b_eoh,
    const float* __restrict__ b_el,
    const void*  __restrict__ etype, const void*  __restrict__ dsti,
    int E)
{
    extern __shared__ char smraw[];
    EdgeSm* sm = (EdgeSm*)smraw;

    const int tid  = threadIdx.x;
    const int e0   = blockIdx.x * 128;
    const int is64 = g_idx64;

    if (tid < 128) {
        int e = e0 + tid;
        if (e < E) {
            sm->stype[tid] = (int)load_idx(etype, e, is64);
            sm->sdst [tid] = (int)load_idx(dsti,  e, is64);
        } else {
            sm->stype[tid] = 0;
            sm->sdst [tid] = -1;
        }
        sm->sbel[tid] = b_el[tid];
    }
    if (tid < 192) sm->sWeoh[tid] = W_eoh[tid];
    if (tid < 64)  sm->sbeoh[tid] = b_eoh[tid];

#pragma unroll
    for (int r = 0; r < 16; ++r) {
        int idx = tid + 256 * r;
        int g2 = idx >> 7, c = idx & 127;
        sm->Bh[g2 * 132 + c] = g_Welh2[idx];
        sm->Bl[g2 * 132 + c] = g_Well2[idx];
    }
    __syncthreads();

    {
        const int el = tid & 127;
        const int g0 = (tid >> 7) * 4;
        const int e  = e0 + el;
        const int t  = sm->stype[el];
        const bool ok = (e < E);
#pragma unroll
        for (int r = 0; r < 8; ++r) {
            int g = g0 + r * 8;
            float4 sv = make_float4(0.f, 0.f, 0.f, 0.f);
            float4 dv = make_float4(0.f, 0.f, 0.f, 0.f);
            if (ok) {
                sv = *(const float4*)&sfeat[(size_t)e * 64 + g];
                dv = *(const float4*)&dfeat[(size_t)e * 64 + g];
            }
            float f0 = fmaf(sv.x, dv.x, sm->sWeoh[(g + 0) * 3 + t] + sm->sbeoh[g + 0]);
            float f1 = fmaf(sv.y, dv.y, sm->sWeoh[(g + 1) * 3 + t] + sm->sbeoh[g + 1]);
            float f2 = fmaf(sv.z, dv.z, sm->sWeoh[(g + 2) * 3 + t] + sm->sbeoh[g + 2]);
            float f3 = fmaf(sv.w, dv.w, sm->sWeoh[(g + 3) * 3 + t] + sm->sbeoh[g + 3]);
            uint32_t hi, lo;
            const int g2 = g >> 1;
            split_pair(f0, f1, hi, lo);
            sm->Ah[g2 * 132 + el] = hi;
            sm->Al[g2 * 132 + el] = lo;
            split_pair(f2, f3, hi, lo);
            sm->Ah[(g2 + 1) * 132 + el] = hi;
            sm->Al[(g2 + 1) * 132 + el] = lo;
        }
    }
    __syncthreads();

    const int lane = tid & 31;
    const int wid  = tid >> 5;
    const int wm   = (wid >> 2) * 64;
    const int wj   = (wid & 3) * 32;
    const int fr   = lane >> 2;
    const int fq   = lane & 3;

    float acc[4][4][4];
#pragma unroll
    for (int i = 0; i < 4; ++i)
#pragma unroll
        for (int j = 0; j < 4; ++j)
#pragma unroll
            for (int r = 0; r < 4; ++r) acc[i][j][r] = 0.f;

#pragma unroll
    for (int c8 = 0; c8 < 32; c8 += 8) {
        uint32_t bh[4][2], bl[4][2];
#pragma unroll
        for (int j = 0; j < 4; ++j) {
            const int col = wj + j * 8 + fr;
            bh[j][0] = sm->Bh[(c8 + fq) * 132 + col];
            bh[j][1] = sm->Bh[(c8 + fq + 4) * 132 + col];
            bl[j][0] = sm->Bl[(c8 + fq) * 132 + col];
            bl[j][1] = sm->Bl[(c8 + fq + 4) * 132 + col];
        }
#pragma unroll
        for (int i = 0; i < 4; ++i) {
            const int row = wm + i * 16 + fr;
            uint32_t ah[4] = { sm->Ah[(c8 + fq) * 132 + row],
                               sm->Ah[(c8 + fq) * 132 + row + 8],
                               sm->Ah[(c8 + fq + 4) * 132 + row],
                               sm->Ah[(c8 + fq + 4) * 132 + row + 8] };
            uint32_t al[4] = { sm->Al[(c8 + fq) * 132 + row],
                               sm->Al[(c8 + fq) * 132 + row + 8],
                               sm->Al[(c8 + fq + 4) * 132 + row],
                               sm->Al[(c8 + fq + 4) * 132 + row + 8] };
#pragma unroll
            for (int j = 0; j < 4; ++j) {
                mma16816(acc[i][j], ah, bh[j]);
                mma16816(acc[i][j], ah, bl[j]);
                mma16816(acc[i][j], al, bh[j]);
            }
        }
    }

    // epilogue A (fragment order): (edge_w + b_el) * h_src -> v2 reds
#pragma unroll
    for (int i = 0; i < 4; ++i) {
#pragma unroll
        for (int half = 0; half < 2; ++half) {
            const int le  = wm + i * 16 + fr + half * 8;
            const int dst = sm->sdst[le];
            if (dst < 0) continue;
            const float* hrow = &h_src[(size_t)(e0 + le) * 128];
            float* orow = &g_hsum[(size_t)dst * 256];
#pragma unroll
            for (int j = 0; j < 4; ++j) {
                const int c = wj + j * 8 + fq * 2;
                float2 h = *(const float2*)&hrow[c];
                float w0 = acc[i][j][half * 2 + 0] + sm->sbel[c];
                float w1 = acc[i][j][half * 2 + 1] + sm->sbel[c + 1];
                red2(&orow[c], w0 * h.x, w1 * h.y);
            }
        }
    }

    // epilogue B: embed + c_src -> v4 reds (coalesced)
    {
        const int tx = tid & 15;
        const int ty = tid >> 4;
#pragma unroll
        for (int i = 0; i < 8; ++i) {
            const int le  = ty * 8 + i;
            const int dst = sm->sdst[le];
            if (dst < 0) continue;
            const int e = e0 + le;
            float4 m0 = *(const float4*)&embed[(size_t)e * 128 + tx * 8];
            float4 m1 = *(const float4*)&embed[(size_t)e * 128 + tx * 8 + 4];
            float* b = &g_hsum[(size_t)dst * 256 + 128 + tx * 8];
            red4(b,     m0.x, m0.y, m0.z, m0.w);
            red4(b + 4, m1.x, m1.y, m1.z, m1.w);
            float4 c0 = *(const float4*)&c_src[(size_t)e * 128 + tx * 8];
            float4 c1 = *(const float4*)&c_src[(size_t)e * 128 + tx * 8 + 4];
            float* cs = &g_csum[(size_t)dst * 128 + tx * 8];
            red4(cs,     c0.x, c0.y, c0.z, c0.w);
            red4(cs + 4, c1.x, c1.y, c1.z, c1.w);
        }
    }
}

// ---------------------------------------------------------------------------
// Gate GEMM via mma.sync bf16 3-term split, B via cp.async double buffer:
//   g_gates[N,512] = act( h_sum[N,256] @ B[256,512] + bias )
// grid (4, ceil(N/128)); 8 warps, warp tile 64x32, k-step 16 (16 chunks).
// ---------------------------------------------------------------------------
__global__ __launch_bounds__(256) void k_mgemm(int N)
{
    __shared__ uint32_t Ah2[2][8][132];
    __shared__ uint32_t Al2[2][8][132];
    __shared__ uint32_t Bh2s[2][8][128];
    __shared__ uint32_t Bl2s[2][8][128];

    const int tid  = threadIdx.x;
    const int lane = tid & 31;
    const int wid  = tid >> 5;
    const int m0   = blockIdx.y * 128;
    const int j0   = blockIdx.x * 128;
    const int wm   = (wid >> 2) * 64;
    const int wj   = (wid & 3) * 32;

    float acc[4][4][4];
#pragma unroll
    for (int i = 0; i < 4; ++i)
#pragma unroll
        for (int j = 0; j < 4; ++j)
#pragma unroll
            for (int r = 0; r < 4; ++r) acc[i][j][r] = 0.f;

    // A staging roles (register prefetch + bf16 split)
    const int  arow = tid >> 1;
    const int  akq  = tid & 1;
    const bool arok = (m0 + arow) < N;
    // B staging roles (cp.async): 256 threads x 16B = 4 KB = one image chunk
    const int  bbr  = tid >> 5;            // row 0..7
    const int  bjc  = (tid & 31) * 4;      // col group

    float4 pa0, pa1;

    auto a_prefetch = [&](int kc) {
        pa0 = make_float4(0.f, 0.f, 0.f, 0.f);
        pa1 = pa0;
        if (arok) {
            const float* src = &g_hsum[(size_t)(m0 + arow) * 256 + kc * 16 + akq * 8];
            pa0 = *(const float4*)(src);
            pa1 = *(const float4*)(src + 4);
        }
    };
    auto a_store = [&](int buf) {
        const int kb = akq * 4;
        split_pair(pa0.x, pa0.y, Ah2[buf][kb + 0][arow], Al2[buf][kb + 0][arow]);
        split_pair(pa0.z, pa0.w, Ah2[buf][kb + 1][arow], Al2[buf][kb + 1][arow]);
        split_pair(pa1.x, pa1.y, Ah2[buf][kb + 2][arow], Al2[buf][kb + 2][arow]);
        split_pair(pa1.z, pa1.w, Ah2[buf][kb + 3][arow], Al2[buf][kb + 3][arow]);
    };
    auto b_issue = [&](int kc, int buf) {
        cp_async16(&Bh2s[buf][bbr][bjc], &g_Bh2[(size_t)(kc * 8 + bbr) * 512 + j0 + bjc]);
        cp_async16(&Bl2s[buf][bbr][bjc], &g_Bl2[(size_t)(kc * 8 + bbr) * 512 + j0 + bjc]);
        CP_COMMIT();
    };

    a_prefetch(0);
    a_store(0);
    b_issue(0, 0);
    CP_WAIT0();
    __syncthreads();

    const int fr = lane >> 2;
    const int fk = lane & 3;

    for (int kc = 0; kc < 16; ++kc) {
        const int cur = kc & 1;
        if (kc < 15) { b_issue(kc + 1, cur ^ 1); a_prefetch(kc + 1); }

        uint32_t bh[4][2], bl[4][2];
#pragma unroll
        for (int j = 0; j < 4; ++j) {
            const int col = wj + j * 8 + fr;
            bh[j][0] = Bh2s[cur][fk][col];
            bh[j][1] = Bh2s[cur][fk + 4][col];
            bl[j][0] = Bl2s[cur][fk][col];
            bl[j][1] = Bl2s[cur][fk + 4][col];
        }
#pragma unroll
        for (int i = 0; i < 4; ++i) {
            const int row = wm + i * 16 + fr;
            uint32_t ah[4] = { Ah2[cur][fk][row], Ah2[cur][fk][row + 8],
                               Ah2[cur][fk + 4][row], Ah2[cur][fk + 4][row + 8] };
            uint32_t al[4] = { Al2[cur][fk][row], Al2[cur][fk][row + 8],
                               Al2[cur][fk + 4][row], Al2[cur][fk + 4][row + 8] };
#pragma unroll
            for (int j = 0; j < 4; ++j) {
                mma16816(acc[i][j], ah, bh[j]);
                mma16816(acc[i][j], ah, bl[j]);
                mma16816(acc[i][j], al, bh[j]);
            }
        }

        if (kc < 15) a_store(cur ^ 1);
        CP_WAIT0();
        __syncthreads();
    }

    const int q = blockIdx.x;   // gate: 0=f 1=i 2=u(tanh) 3=o
#pragma unroll
    for (int j = 0; j < 4; ++j) {
        const int c = j0 + wj + j * 8 + (lane & 3) * 2;
        const float b0 = g_bias[c], b1 = g_bias[c + 1];
#pragma unroll
        for (int i = 0; i < 4; ++i) {
            const int mr = m0 + wm + i * 16 + (lane >> 2);
#pragma unroll
            for (int half = 0; half < 2; ++half) {
                const int m = mr + half * 8;
                if (m >= N) continue;
                float v0 = acc[i][j][half * 2 + 0] + b0;
                float v1 = acc[i][j][half * 2 + 1] + b1;
                float2 o;
                if (q == 2) { o.x = tanhf(v0); o.y = tanhf(v1); }
                else        { o.x = 1.f / (1.f + expf(-v0)); o.y = 1.f / (1.f + expf(-v1)); }
                *(float2*)&g_gates[(size_t)m * 512 + c] = o;
            }
        }
    }
}

// ---------------------------------------------------------------------------
// Finalize: c = i*u + f*c_sum ; h = o*tanh(c) ; out = [h | c]   (R12-exact)
// ---------------------------------------------------------------------------
__global__ void k_final(float* __restrict__ out, int N)
{
    int id = blockIdx.x * blockDim.x + threadIdx.x;
    int n  = id >> 5;
    if (n >= N) return;
    int h4 = (id & 31) * 4;
    const float* gr = &g_gates[(size_t)n * 512];
    float4 fg = *(const float4*)&gr[0   + h4];
    float4 ig = *(const float4*)&gr[128 + h4];
    float4 ug = *(const float4*)&gr[256 + h4];
    float4 og = *(const float4*)&gr[384 + h4];
    float4 cs = *(const float4*)&g_csum[(size_t)n * 128 + h4];
    float4 c, h;
    c.x = fmaf(ig.x, ug.x, fg.x * cs.x);  h.x = og.x * tanhf(c.x);
    c.y = fmaf(ig.y, ug.y, fg.y * cs.y);  h.y = og.y * tanhf(c.y);
    c.z = fmaf(ig.z, ug.z, fg.z * cs.z);  h.z = og.z * tanhf(c.z);
    c.w = fmaf(ig.w, ug.w, fg.w * cs.w);  h.w = og.w * tanhf(c.w);
    *(float4*)&out[(size_t)n * 256 + h4]       = h;
    *(float4*)&out[(size_t)n * 256 + 128 + h4] = c;
}

// ---------------------------------------------------------------------------
// Launch
// ---------------------------------------------------------------------------
extern "C" void kernel_launch(void* const* d_in, const int* in_sizes, int n_in,
                              void* d_out, int out_size)
{
    const float* h_src = (const float*)d_in[0];
    const float* c_src = (const float*)d_in[1];
    const float* embed = (const float*)d_in[2];
    const float* sfeat = (const float*)d_in[3];
    const float* dfeat = (const float*)d_in[4];
    const float* Wf  = (const float*)d_in[5];
    const float* bWf = (const float*)d_in[6];
    const float* bf  = (const float*)d_in[7];
    const float* Wi  = (const float*)d_in[8];
    const float* bWi = (const float*)d_in[9];
    const float* bi  = (const float*)d_in[10];
    const float* Wu  = (const float*)d_in[11];
    const float* bWu = (const float*)d_in[12];
    const float* bu  = (const float*)d_in[13];
    const float* Wo  = (const float*)d_in[14];
    const float* bWo = (const float*)d_in[15];
    const float* bo  = (const float*)d_in[16];
    const float* W_eoh = (const float*)d_in[17];
    const float* b_eoh = (const float*)d_in[18];
    const float* W_el  = (const float*)d_in[19];
    const float* b_el  = (const float*)d_in[20];
    const void*  etype = d_in[21];
    const void*  dsti  = d_in[22];

    const int E = in_sizes[0] / 128;
    const int N = out_size   / 256;

    cudaFuncSetAttribute(k_edgemm, cudaFuncAttributeMaxDynamicSharedMemorySize,
                         (int)sizeof(EdgeSm));

    // 1) zero scatter targets via driver memsets (3 ops -> shifts ncu's
    //    capture index 5 onto k_mgemm for next round's profile)
    void *p_hsum = nullptr, *p_csum = nullptr;
    cudaGetSymbolAddress(&p_hsum, g_hsum);
    cudaGetSymbolAddress(&p_csum, g_csum);
    size_t half = (size_t)N * 128 * sizeof(float);
    cudaMemsetAsync(p_hsum, 0, half);
    cudaMemsetAsync((char*)p_hsum + half, 0, half);
    cudaMemsetAsync(p_csum, 0, (size_t)N * 128 * sizeof(float));

    // 2) merged setup: weight/bias packing + index dtype probe
    k_setup<<<275, 256>>>(Wf, Wi, Wu, Wo, bWf, bf, bWi, bi, bWu, bu, bWo, bo,
                          W_el, (const unsigned int*)dsti);

    // 3) edge-message GEMM (tensor) + scatter h_sum / c_sum
    k_edgemm<<<(E + 127) / 128, 256, sizeof(EdgeSm)>>>(
        h_src, embed, c_src, sfeat, dfeat, W_eoh, b_eoh, b_el, etype, dsti, E);

    // 4) gate GEMM (mma.sync bf16 3-term, cp.async B) + activations
    dim3 gg(4, (N + 127) / 128);
    k_mgemm<<<gg, 256>>>(N);

    // 5) finalize:  c = i*u + f*c_sum ; h = o*tanh(c)
    k_final<<<(N * 32 + 255) / 256, 256>>>((float*)d_out, N);
}

// round 15
// speedup vs baseline: 1.0929x; 1.0929x over previous
#include <cuda_runtime.h>
#include <cuda_bf16.h>
#include <cuda_fp16.h>
#include <math.h>
#include <stdint.h>

// ---------------------------------------------------------------------------
// Problem constants
// ---------------------------------------------------------------------------
#define MAXN 125000
#define MAXE 500000

// Scratch (device globals -- no allocation allowed)
__device__ float  g_hsum [(size_t)MAXN * 256];   // [N, H+X] segment sum
__device__ __half g_gates[(size_t)MAXN * 512];   // activated gates f,i,u,o (fp16)
__device__ float  g_csum [(size_t)MAXN * 128];   // segment_sum(c_src)  [N, H]
__device__ float  g_bias [512];                  // bW* + b*
__device__ uint32_t g_Bh2[128 * 512];            // gate W hi: bf16x2 pairs along K  [k2][j]
__device__ uint32_t g_Bl2[128 * 512];            // gate W lo
__device__ uint32_t g_Welh2[32 * 128];           // W_el hi: bf16x2 pairs along g  [g2][c]
__device__ uint32_t g_Well2[32 * 128];           // W_el lo
__device__ int   g_idx64;

// ---------------------------------------------------------------------------
// Helpers
// ---------------------------------------------------------------------------
__device__ __forceinline__ uint32_t packbf2(float x, float y)
{
    __nv_bfloat162 p = __floats2bfloat162_rn(x, y);
    return *(uint32_t*)&p;
}

__device__ __forceinline__ void split_pair(float x, float y, uint32_t& hi, uint32_t& lo)
{
    __nv_bfloat16 hx = __float2bfloat16(x);
    __nv_bfloat16 hy = __float2bfloat16(y);
    __nv_bfloat162 hp; hp.x = hx; hp.y = hy;
    hi = *(uint32_t*)&hp;
    lo = packbf2(x - __bfloat162float(hx), y - __bfloat162float(hy));
}

__device__ __forceinline__ void mma16816(float* d, const uint32_t* a, const uint32_t* b)
{
    asm volatile(
        "mma.sync.aligned.m16n8k16.row.col.f32.bf16.bf16.f32 "
        "{%0,%1,%2,%3}, {%4,%5,%6,%7}, {%8,%9}, {%0,%1,%2,%3};"
        : "+f"(d[0]), "+f"(d[1]), "+f"(d[2]), "+f"(d[3])
        : "r"(a[0]), "r"(a[1]), "r"(a[2]), "r"(a[3]), "r"(b[0]), "r"(b[1]));
}

__device__ __forceinline__ void red4(float* addr, float a, float b, float c, float d)
{
    asm volatile("red.global.add.v4.f32 [%0], {%1, %2, %3, %4};"
                 :: "l"(addr), "f"(a), "f"(b), "f"(c), "f"(d) : "memory");
}
__device__ __forceinline__ void red2(float* addr, float a, float b)
{
    asm volatile("red.global.add.v2.f32 [%0], {%1, %2};"
                 :: "l"(addr), "f"(a), "f"(b) : "memory");
}

__device__ __forceinline__ long long load_idx(const void* p, int i, int is64)
{
    return is64 ? ((const long long*)p)[i] : (long long)((const int*)p)[i];
}

// ---------------------------------------------------------------------------
// Merged setup kernel: packB + W_el pairs + biases + index-dtype detect.
// ---------------------------------------------------------------------------
__global__ void k_setup(const float* __restrict__ Wf, const float* __restrict__ Wi,
                        const float* __restrict__ Wu, const float* __restrict__ Wo,
                        const float* __restrict__ bWf, const float* __restrict__ bf,
                        const float* __restrict__ bWi, const float* __restrict__ bi,
                        const float* __restrict__ bWu, const float* __restrict__ bu,
                        const float* __restrict__ bWo, const float* __restrict__ bo,
                        const float* __restrict__ W_el,
                        const unsigned int* __restrict__ dwords)
{
    int id = blockIdx.x * blockDim.x + threadIdx.x;
    if (id < 65536) {                       // gate weights
        int k2 = id >> 9;
        int j  = id & 511;
        int q = j >> 7, jj = j & 127;
        const float* W = (q == 0) ? Wf : (q == 1) ? Wi : (q == 2) ? Wu : Wo;
        float w0 = W[jj * 256 + 2 * k2];
        float w1 = W[jj * 256 + 2 * k2 + 1];
        uint32_t hi, lo;
        split_pair(w0, w1, hi, lo);
        g_Bh2[id] = hi;
        g_Bl2[id] = lo;
    } else if (id < 65536 + 4096) {         // W_el pairs
        int t = id - 65536;
        int g2 = t >> 7, c = t & 127;
        float w0 = W_el[c * 64 + 2 * g2];
        float w1 = W_el[c * 64 + 2 * g2 + 1];
        uint32_t hi, lo;
        split_pair(w0, w1, hi, lo);
        g_Welh2[t] = hi;
        g_Well2[t] = lo;
    } else if (id < 69632 + 512) {          // biases
        int t = id - 69632;
        int q = t >> 7, j = t & 127;
        const float* bW = (q == 0) ? bWf : (q == 1) ? bWi : (q == 2) ? bWu : bWo;
        const float* bb = (q == 0) ? bf  : (q == 1) ? bi  : (q == 2) ? bu  : bo;
        g_bias[t] = bW[j] + bb[j];
    } else if (id == 70144) {               // index dtype probe
        int all_hi_zero = 1;
        for (int k = 0; k < 64; ++k)
            if (dwords[2 * k + 1] != 0u) { all_hi_zero = 0; break; }
        g_idx64 = all_hi_zero;
    }
}

// ---------------------------------------------------------------------------
// Edge-message GEMM (mma.sync bf16 3-term) + scatter.  (R8/R12-exact)
// ---------------------------------------------------------------------------
struct EdgeSm {
    uint32_t Ah[32 * 132];
    uint32_t Al[32 * 132];
    uint32_t Bh[32 * 132];
    uint32_t Bl[32 * 132];
    int   sdst[128];
    int   stype[128];
    float sWeoh[192];
    float sbeoh[64];
    float sbel[128];
};

__global__ __launch_bounds__(256, 2) void k_edgemm(
    const float* __restrict__ h_src, const float* __restrict__ embed,
    const float* __restrict__ c_src,
    const float* __restrict__ sfeat, const float* __restrict__ dfeat,
    const float* __restrict__ W_eoh, const float* __restrict__ b_eoh,
    const float* __restrict__ b_el,
    const void*  __restrict__ etype, const void*  __restrict__ dsti,
    int E)
{
    extern __shared__ char smraw[];
    EdgeSm* sm = (EdgeSm*)smraw;

    const int tid  = threadIdx.x;
    const int e0   = blockIdx.x * 128;
    const int is64 = g_idx64;

    if (tid < 128) {
        int e = e0 + tid;
        if (e < E) {
            sm->stype[tid] = (int)load_idx(etype, e, is64);
            sm->sdst [tid] = (int)load_idx(dsti,  e, is64);
        } else {
            sm->stype[tid] = 0;
            sm->sdst [tid] = -1;
        }
        sm->sbel[tid] = b_el[tid];
    }
    if (tid < 192) sm->sWeoh[tid] = W_eoh[tid];
    if (tid < 64)  sm->sbeoh[tid] = b_eoh[tid];

#pragma unroll
    for (int r = 0; r < 16; ++r) {
        int idx = tid + 256 * r;
        int g2 = idx >> 7, c = idx & 127;
        sm->Bh[g2 * 132 + c] = g_Welh2[idx];
        sm->Bl[g2 * 132 + c] = g_Well2[idx];
    }
    __syncthreads();

    {
        const int el = tid & 127;
        const int g0 = (tid >> 7) * 4;
        const int e  = e0 + el;
        const int t  = sm->stype[el];
        const bool ok = (e < E);
#pragma unroll
        for (int r = 0; r < 8; ++r) {
            int g = g0 + r * 8;
            float4 sv = make_float4(0.f, 0.f, 0.f, 0.f);
            float4 dv = make_float4(0.f, 0.f, 0.f, 0.f);
            if (ok) {
                sv = *(const float4*)&sfeat[(size_t)e * 64 + g];
                dv = *(const float4*)&dfeat[(size_t)e * 64 + g];
            }
            float f0 = fmaf(sv.x, dv.x, sm->sWeoh[(g + 0) * 3 + t] + sm->sbeoh[g + 0]);
            float f1 = fmaf(sv.y, dv.y, sm->sWeoh[(g + 1) * 3 + t] + sm->sbeoh[g + 1]);
            float f2 = fmaf(sv.z, dv.z, sm->sWeoh[(g + 2) * 3 + t] + sm->sbeoh[g + 2]);
            float f3 = fmaf(sv.w, dv.w, sm->sWeoh[(g + 3) * 3 + t] + sm->sbeoh[g + 3]);
            uint32_t hi, lo;
            const int g2 = g >> 1;
            split_pair(f0, f1, hi, lo);
            sm->Ah[g2 * 132 + el] = hi;
            sm->Al[g2 * 132 + el] = lo;
            split_pair(f2, f3, hi, lo);
            sm->Ah[(g2 + 1) * 132 + el] = hi;
            sm->Al[(g2 + 1) * 132 + el] = lo;
        }
    }
    __syncthreads();

    const int lane = tid & 31;
    const int wid  = tid >> 5;
    const int wm   = (wid >> 2) * 64;
    const int wj   = (wid & 3) * 32;
    const int fr   = lane >> 2;
    const int fq   = lane & 3;

    float acc[4][4][4];
#pragma unroll
    for (int i = 0; i < 4; ++i)
#pragma unroll
        for (int j = 0; j < 4; ++j)
#pragma unroll
            for (int r = 0; r < 4; ++r) acc[i][j][r] = 0.f;

#pragma unroll
    for (int c8 = 0; c8 < 32; c8 += 8) {
        uint32_t bh[4][2], bl[4][2];
#pragma unroll
        for (int j = 0; j < 4; ++j) {
            const int col = wj + j * 8 + fr;
            bh[j][0] = sm->Bh[(c8 + fq) * 132 + col];
            bh[j][1] = sm->Bh[(c8 + fq + 4) * 132 + col];
            bl[j][0] = sm->Bl[(c8 + fq) * 132 + col];
            bl[j][1] = sm->Bl[(c8 + fq + 4) * 132 + col];
        }
#pragma unroll
        for (int i = 0; i < 4; ++i) {
            const int row = wm + i * 16 + fr;
            uint32_t ah[4] = { sm->Ah[(c8 + fq) * 132 + row],
                               sm->Ah[(c8 + fq) * 132 + row + 8],
                               sm->Ah[(c8 + fq + 4) * 132 + row],
                               sm->Ah[(c8 + fq + 4) * 132 + row + 8] };
            uint32_t al[4] = { sm->Al[(c8 + fq) * 132 + row],
                               sm->Al[(c8 + fq) * 132 + row + 8],
                               sm->Al[(c8 + fq + 4) * 132 + row],
                               sm->Al[(c8 + fq + 4) * 132 + row + 8] };
#pragma unroll
            for (int j = 0; j < 4; ++j) {
                mma16816(acc[i][j], ah, bh[j]);
                mma16816(acc[i][j], ah, bl[j]);
                mma16816(acc[i][j], al, bh[j]);
            }
        }
    }

    // epilogue A (fragment order): (edge_w + b_el) * h_src -> v2 reds
#pragma unroll
    for (int i = 0; i < 4; ++i) {
#pragma unroll
        for (int half = 0; half < 2; ++half) {
            const int le  = wm + i * 16 + fr + half * 8;
            const int dst = sm->sdst[le];
            if (dst < 0) continue;
            const float* hrow = &h_src[(size_t)(e0 + le) * 128];
            float* orow = &g_hsum[(size_t)dst * 256];
#pragma unroll
            for (int j = 0; j < 4; ++j) {
                const int c = wj + j * 8 + fq * 2;
                float2 h = *(const float2*)&hrow[c];
                float w0 = acc[i][j][half * 2 + 0] + sm->sbel[c];
                float w1 = acc[i][j][half * 2 + 1] + sm->sbel[c + 1];
                red2(&orow[c], w0 * h.x, w1 * h.y);
            }
        }
    }

    // epilogue B: embed + c_src -> v4 reds (coalesced)
    {
        const int tx = tid & 15;
        const int ty = tid >> 4;
#pragma unroll
        for (int i = 0; i < 8; ++i) {
            const int le  = ty * 8 + i;
            const int dst = sm->sdst[le];
            if (dst < 0) continue;
            const int e = e0 + le;
            float4 m0 = *(const float4*)&embed[(size_t)e * 128 + tx * 8];
            float4 m1 = *(const float4*)&embed[(size_t)e * 128 + tx * 8 + 4];
            float* b = &g_hsum[(size_t)dst * 256 + 128 + tx * 8];
            red4(b,     m0.x, m0.y, m0.z, m0.w);
            red4(b + 4, m1.x, m1.y, m1.z, m1.w);
            float4 c0 = *(const float4*)&c_src[(size_t)e * 128 + tx * 8];
            float4 c1 = *(const float4*)&c_src[(size_t)e * 128 + tx * 8 + 4];
            float* cs = &g_csum[(size_t)dst * 128 + tx * 8];
            red4(cs,     c0.x, c0.y, c0.z, c0.w);
            red4(cs + 4, c1.x, c1.y, c1.z, c1.w);
        }
    }
}

// ---------------------------------------------------------------------------
// Gate GEMM via mma.sync bf16 3-term split, double-buffered (R12-exact core):
//   g_gates[N,512](fp16) = act( h_sum[N,256] @ B[256,512] + bias )
// ---------------------------------------------------------------------------
__global__ __launch_bounds__(256) void k_mgemm(int N)
{
    __shared__ uint32_t Ah2[2][8][132];
    __shared__ uint32_t Al2[2][8][132];
    __shared__ uint32_t Bh2[2][8][132];
    __shared__ uint32_t Bl2[2][8][132];

    const int tid  = threadIdx.x;
    const int lane = tid & 31;
    const int wid  = tid >> 5;
    const int m0   = blockIdx.y * 128;
    const int j0   = blockIdx.x * 128;
    const int wm   = (wid >> 2) * 64;
    const int wj   = (wid & 3) * 32;

    float acc[4][4][4];
#pragma unroll
    for (int i = 0; i < 4; ++i)
#pragma unroll
        for (int j = 0; j < 4; ++j)
#pragma unroll
            for (int r = 0; r < 4; ++r) acc[i][j][r] = 0.f;

    const int  arow = tid >> 1;
    const int  akq  = tid & 1;
    const bool arok = (m0 + arow) < N;
    const int  bbr  = tid >> 5;
    const int  bjc  = (tid & 31) * 4;

    float4 pa0, pa1;
    uint4  pbh, pbl;

    auto prefetch = [&](int kc) {
        pa0 = make_float4(0.f, 0.f, 0.f, 0.f);
        pa1 = pa0;
        if (arok) {
            const float* src = &g_hsum[(size_t)(m0 + arow) * 256 + kc * 16 + akq * 8];
            pa0 = *(const float4*)(src);
            pa1 = *(const float4*)(src + 4);
        }
        pbh = *(const uint4*)&g_Bh2[(size_t)(kc * 8 + bbr) * 512 + j0 + bjc];
        pbl = *(const uint4*)&g_Bl2[(size_t)(kc * 8 + bbr) * 512 + j0 + bjc];
    };
    auto store_chunk = [&](int buf) {
        const int kb = akq * 4;
        split_pair(pa0.x, pa0.y, Ah2[buf][kb + 0][arow], Al2[buf][kb + 0][arow]);
        split_pair(pa0.z, pa0.w, Ah2[buf][kb + 1][arow], Al2[buf][kb + 1][arow]);
        split_pair(pa1.x, pa1.y, Ah2[buf][kb + 2][arow], Al2[buf][kb + 2][arow]);
        split_pair(pa1.z, pa1.w, Ah2[buf][kb + 3][arow], Al2[buf][kb + 3][arow]);
        *(uint4*)&Bh2[buf][bbr][bjc] = pbh;
        *(uint4*)&Bl2[buf][bbr][bjc] = pbl;
    };

    prefetch(0);
    store_chunk(0);
    __syncthreads();

    const int fr = lane >> 2;
    const int fk = lane & 3;

    for (int kc = 0; kc < 16; ++kc) {
        const int cur = kc & 1;
        if (kc < 15) prefetch(kc + 1);

        uint32_t bh[4][2], bl[4][2];
#pragma unroll
        for (int j = 0; j < 4; ++j) {
            const int col = wj + j * 8 + fr;
            bh[j][0] = Bh2[cur][fk][col];
            bh[j][1] = Bh2[cur][fk + 4][col];
            bl[j][0] = Bl2[cur][fk][col];
            bl[j][1] = Bl2[cur][fk + 4][col];
        }
#pragma unroll
        for (int i = 0; i < 4; ++i) {
            const int row = wm + i * 16 + fr;
            uint32_t ah[4] = { Ah2[cur][fk][row], Ah2[cur][fk][row + 8],
                               Ah2[cur][fk + 4][row], Ah2[cur][fk + 4][row + 8] };
            uint32_t al[4] = { Al2[cur][fk][row], Al2[cur][fk][row + 8],
                               Al2[cur][fk + 4][row], Al2[cur][fk + 4][row + 8] };
#pragma unroll
            for (int j = 0; j < 4; ++j) {
                mma16816(acc[i][j], ah, bh[j]);
                mma16816(acc[i][j], ah, bl[j]);
                mma16816(acc[i][j], al, bh[j]);
            }
        }

        if (kc < 15) store_chunk(cur ^ 1);
        __syncthreads();
    }

    const int q = blockIdx.x;   // gate: 0=f 1=i 2=u(tanh) 3=o
#pragma unroll
    for (int j = 0; j < 4; ++j) {
        const int c = j0 + wj + j * 8 + (lane & 3) * 2;
        const float b0 = g_bias[c], b1 = g_bias[c + 1];
#pragma unroll
        for (int i = 0; i < 4; ++i) {
            const int mr = m0 + wm + i * 16 + (lane >> 2);
#pragma unroll
            for (int half = 0; half < 2; ++half) {
                const int m = mr + half * 8;
                if (m >= N) continue;
                float v0 = acc[i][j][half * 2 + 0] + b0;
                float v1 = acc[i][j][half * 2 + 1] + b1;
                float o0, o1;
                if (q == 2) { o0 = tanhf(v0); o1 = tanhf(v1); }
                else        { o0 = 1.f / (1.f + expf(-v0)); o1 = 1.f / (1.f + expf(-v1)); }
                *(__half2*)&g_gates[(size_t)m * 512 + c] = __floats2half2_rn(o0, o1);
            }
        }
    }
}

// ---------------------------------------------------------------------------
// Finalize: c = i*u + f*c_sum ; h = o*tanh(c) ; out = [h | c]
// Gates read as fp16 (half traffic of fp32 version).
// ---------------------------------------------------------------------------
__global__ void k_final(float* __restrict__ out, int N)
{
    int id = blockIdx.x * blockDim.x + threadIdx.x;
    int n  = id >> 5;
    if (n >= N) return;
    int h4 = (id & 31) * 4;
    const __half* gr = &g_gates[(size_t)n * 512];

    uint2 uf = *(const uint2*)&gr[0   + h4];
    uint2 ui = *(const uint2*)&gr[128 + h4];
    uint2 uu = *(const uint2*)&gr[256 + h4];
    uint2 uo = *(const uint2*)&gr[384 + h4];
    float2 f01 = __half22float2(*(__half2*)&uf.x), f23 = __half22float2(*(__half2*)&uf.y);
    float2 i01 = __half22float2(*(__half2*)&ui.x), i23 = __half22float2(*(__half2*)&ui.y);
    float2 u01 = __half22float2(*(__half2*)&uu.x), u23 = __half22float2(*(__half2*)&uu.y);
    float2 o01 = __half22float2(*(__half2*)&uo.x), o23 = __half22float2(*(__half2*)&uo.y);

    float4 cs = *(const float4*)&g_csum[(size_t)n * 128 + h4];
    float4 c, h;
    c.x = fmaf(i01.x, u01.x, f01.x * cs.x);  h.x = o01.x * tanhf(c.x);
    c.y = fmaf(i01.y, u01.y, f01.y * cs.y);  h.y = o01.y * tanhf(c.y);
    c.z = fmaf(i23.x, u23.x, f23.x * cs.z);  h.z = o23.x * tanhf(c.z);
    c.w = fmaf(i23.y, u23.y, f23.y * cs.w);  h.w = o23.y * tanhf(c.w);
    *(float4*)&out[(size_t)n * 256 + h4]       = h;
    *(float4*)&out[(size_t)n * 256 + 128 + h4] = c;
}

// ---------------------------------------------------------------------------
// Launch
// ---------------------------------------------------------------------------
extern "C" void kernel_launch(void* const* d_in, const int* in_sizes, int n_in,
                              void* d_out, int out_size)
{
    const float* h_src = (const float*)d_in[0];
    const float* c_src = (const float*)d_in[1];
    const float* embed = (const float*)d_in[2];
    const float* sfeat = (const float*)d_in[3];
    const float* dfeat = (const float*)d_in[4];
    const float* Wf  = (const float*)d_in[5];
    const float* bWf = (const float*)d_in[6];
    const float* bf  = (const float*)d_in[7];
    const float* Wi  = (const float*)d_in[8];
    const float* bWi = (const float*)d_in[9];
    const float* bi  = (const float*)d_in[10];
    const float* Wu  = (const float*)d_in[11];
    const float* bWu = (const float*)d_in[12];
    const float* bu  = (const float*)d_in[13];
    const float* Wo  = (const float*)d_in[14];
    const float* bWo = (const float*)d_in[15];
    const float* bo  = (const float*)d_in[16];
    const float* W_eoh = (const float*)d_in[17];
    const float* b_eoh = (const float*)d_in[18];
    const float* W_el  = (const float*)d_in[19];
    const float* b_el  = (const float*)d_in[20];
    const void*  etype = d_in[21];
    const void*  dsti  = d_in[22];

    const int E = in_sizes[0] / 128;
    const int N = out_size   / 256;

    cudaFuncSetAttribute(k_edgemm, cudaFuncAttributeMaxDynamicSharedMemorySize,
                         (int)sizeof(EdgeSm));

    // 1) zero scatter targets via driver memsets
    void *p_hsum = nullptr, *p_csum = nullptr;
    cudaGetSymbolAddress(&p_hsum, g_hsum);
    cudaGetSymbolAddress(&p_csum, g_csum);
    cudaMemsetAsync(p_hsum, 0, (size_t)N * 256 * sizeof(float));
    cudaMemsetAsync(p_csum, 0, (size_t)N * 128 * sizeof(float));

    // 2) merged setup: weight/bias packing + index dtype probe
    k_setup<<<275, 256>>>(Wf, Wi, Wu, Wo, bWf, bf, bWi, bi, bWu, bu, bWo, bo,
                          W_el, (const unsigned int*)dsti);

    // 3) edge-message GEMM (tensor) + scatter h_sum / c_sum
    k_edgemm<<<(E + 127) / 128, 256, sizeof(EdgeSm)>>>(
        h_src, embed, c_src, sfeat, dfeat, W_eoh, b_eoh, b_el, etype, dsti, E);

    // 4) gate GEMM (mma.sync bf16 3-term, double-buffered) + activations (fp16 out)
    dim3 gg(4, (N + 127) / 128);
    k_mgemm<<<gg, 256>>>(N);

    // 5) finalize:  c = i*u + f*c_sum ; h = o*tanh(c)
    k_final<<<(N * 32 + 255) / 256, 256>>>((float*)d_out, N);
}

// round 16
// speedup vs baseline: 1.1363x; 1.0397x over previous
#include <cuda_runtime.h>
#include <cuda_bf16.h>
#include <cuda_fp16.h>
#include <math.h>
#include <stdint.h>

// ---------------------------------------------------------------------------
// Problem constants
// ---------------------------------------------------------------------------
#define MAXN 125000
#define MAXE 500000

// Scratch (device globals -- no allocation allowed)
__device__ float  g_hsum [(size_t)MAXN * 256];   // [N, H+X] segment sum
__device__ __half g_gates[(size_t)MAXN * 512];   // activated gates f,i,u,o (fp16)
__device__ float  g_csum [(size_t)MAXN * 128];   // segment_sum(c_src)  [N, H]
__device__ float  g_bias [512];                  // bW* + b*
__device__ uint32_t g_Bh2[128 * 512];            // gate W hi: bf16x2 pairs along K  [k2][j]
__device__ uint32_t g_Bl2[128 * 512];            // gate W lo
__device__ uint32_t g_Welh2[32 * 128];           // W_el hi: bf16x2 pairs along g  [g2][c]
__device__ uint32_t g_Well2[32 * 128];           // W_el lo
__device__ int   g_idx64;

// ---------------------------------------------------------------------------
// Helpers
// ---------------------------------------------------------------------------
__device__ __forceinline__ uint32_t packbf2(float x, float y)
{
    __nv_bfloat162 p = __floats2bfloat162_rn(x, y);
    return *(uint32_t*)&p;
}

__device__ __forceinline__ void split_pair(float x, float y, uint32_t& hi, uint32_t& lo)
{
    __nv_bfloat16 hx = __float2bfloat16(x);
    __nv_bfloat16 hy = __float2bfloat16(y);
    __nv_bfloat162 hp; hp.x = hx; hp.y = hy;
    hi = *(uint32_t*)&hp;
    lo = packbf2(x - __bfloat162float(hx), y - __bfloat162float(hy));
}

__device__ __forceinline__ void mma16816(float* d, const uint32_t* a, const uint32_t* b)
{
    asm volatile(
        "mma.sync.aligned.m16n8k16.row.col.f32.bf16.bf16.f32 "
        "{%0,%1,%2,%3}, {%4,%5,%6,%7}, {%8,%9}, {%0,%1,%2,%3};"
        : "+f"(d[0]), "+f"(d[1]), "+f"(d[2]), "+f"(d[3])
        : "r"(a[0]), "r"(a[1]), "r"(a[2]), "r"(a[3]), "r"(b[0]), "r"(b[1]));
}

__device__ __forceinline__ void red4(float* addr, float a, float b, float c, float d)
{
    asm volatile("red.global.add.v4.f32 [%0], {%1, %2, %3, %4};"
                 :: "l"(addr), "f"(a), "f"(b), "f"(c), "f"(d) : "memory");
}
__device__ __forceinline__ void red2(float* addr, float a, float b)
{
    asm volatile("red.global.add.v2.f32 [%0], {%1, %2};"
                 :: "l"(addr), "f"(a), "f"(b) : "memory");
}

__device__ __forceinline__ long long load_idx(const void* p, int i, int is64)
{
    return is64 ? ((const long long*)p)[i] : (long long)((const int*)p)[i];
}

// Fast activations: 2 MUFU + ~3 instr each (vs ~17 for accurate versions).
// Rel error ~1e-6 -- negligible against the 2e-4 from fp16 gate storage.
__device__ __forceinline__ float sigmoid_fast(float x)
{
    float e = __expf(-x);
    return __fdividef(1.f, 1.f + e);
}
__device__ __forceinline__ float tanh_fast(float x)
{
    float xc = fminf(x, 15.f);           // avoid inf/inf; tanh(15) == 1 in fp32
    float e  = __expf(2.f * xc);
    return __fdividef(e - 1.f, e + 1.f);
}

// ---------------------------------------------------------------------------
// Merged setup kernel: packB + W_el pairs + biases + index-dtype detect.
// ---------------------------------------------------------------------------
__global__ void k_setup(const float* __restrict__ Wf, const float* __restrict__ Wi,
                        const float* __restrict__ Wu, const float* __restrict__ Wo,
                        const float* __restrict__ bWf, const float* __restrict__ bf,
                        const float* __restrict__ bWi, const float* __restrict__ bi,
                        const float* __restrict__ bWu, const float* __restrict__ bu,
                        const float* __restrict__ bWo, const float* __restrict__ bo,
                        const float* __restrict__ W_el,
                        const unsigned int* __restrict__ dwords)
{
    int id = blockIdx.x * blockDim.x + threadIdx.x;
    if (id < 65536) {                       // gate weights
        int k2 = id >> 9;
        int j  = id & 511;
        int q = j >> 7, jj = j & 127;
        const float* W = (q == 0) ? Wf : (q == 1) ? Wi : (q == 2) ? Wu : Wo;
        float w0 = W[jj * 256 + 2 * k2];
        float w1 = W[jj * 256 + 2 * k2 + 1];
        uint32_t hi, lo;
        split_pair(w0, w1, hi, lo);
        g_Bh2[id] = hi;
        g_Bl2[id] = lo;
    } else if (id < 65536 + 4096) {         // W_el pairs
        int t = id - 65536;
        int g2 = t >> 7, c = t & 127;
        float w0 = W_el[c * 64 + 2 * g2];
        float w1 = W_el[c * 64 + 2 * g2 + 1];
        uint32_t hi, lo;
        split_pair(w0, w1, hi, lo);
        g_Welh2[t] = hi;
        g_Well2[t] = lo;
    } else if (id < 69632 + 512) {          // biases
        int t = id - 69632;
        int q = t >> 7, j = t & 127;
        const float* bW = (q == 0) ? bWf : (q == 1) ? bWi : (q == 2) ? bWu : bWo;
        const float* bb = (q == 0) ? bf  : (q == 1) ? bi  : (q == 2) ? bu  : bo;
        g_bias[t] = bW[j] + bb[j];
    } else if (id == 70144) {               // index dtype probe
        int all_hi_zero = 1;
        for (int k = 0; k < 64; ++k)
            if (dwords[2 * k + 1] != 0u) { all_hi_zero = 0; break; }
        g_idx64 = all_hi_zero;
    }
}

// ---------------------------------------------------------------------------
// Edge-message GEMM (mma.sync bf16 3-term) + scatter.  (R8/R12-exact)
// ---------------------------------------------------------------------------
struct EdgeSm {
    uint32_t Ah[32 * 132];
    uint32_t Al[32 * 132];
    uint32_t Bh[32 * 132];
    uint32_t Bl[32 * 132];
    int   sdst[128];
    int   stype[128];
    float sWeoh[192];
    float sbeoh[64];
    float sbel[128];
};

__global__ __launch_bounds__(256, 2) void k_edgemm(
    const float* __restrict__ h_src, const float* __restrict__ embed,
    const float* __restrict__ c_src,
    const float* __restrict__ sfeat, const float* __restrict__ dfeat,
    const float* __restrict__ W_eoh, const float* __restrict__ b_eoh,
    const float* __restrict__ b_el,
    const void*  __restrict__ etype, const void*  __restrict__ dsti,
    int E)
{
    extern __shared__ char smraw[];
    EdgeSm* sm = (EdgeSm*)smraw;

    const int tid  = threadIdx.x;
    const int e0   = blockIdx.x * 128;
    const int is64 = g_idx64;

    if (tid < 128) {
        int e = e0 + tid;
        if (e < E) {
            sm->stype[tid] = (int)load_idx(etype, e, is64);
            sm->sdst [tid] = (int)load_idx(dsti,  e, is64);
        } else {
            sm->stype[tid] = 0;
            sm->sdst [tid] = -1;
        }
        sm->sbel[tid] = b_el[tid];
    }
    if (tid < 192) sm->sWeoh[tid] = W_eoh[tid];
    if (tid < 64)  sm->sbeoh[tid] = b_eoh[tid];

#pragma unroll
    for (int r = 0; r < 16; ++r) {
        int idx = tid + 256 * r;
        int g2 = idx >> 7, c = idx & 127;
        sm->Bh[g2 * 132 + c] = g_Welh2[idx];
        sm->Bl[g2 * 132 + c] = g_Well2[idx];
    }
    __syncthreads();

    {
        const int el = tid & 127;
        const int g0 = (tid >> 7) * 4;
        const int e  = e0 + el;
        const int t  = sm->stype[el];
        const bool ok = (e < E);
#pragma unroll
        for (int r = 0; r < 8; ++r) {
            int g = g0 + r * 8;
            float4 sv = make_float4(0.f, 0.f, 0.f, 0.f);
            float4 dv = make_float4(0.f, 0.f, 0.f, 0.f);
            if (ok) {
                sv = *(const float4*)&sfeat[(size_t)e * 64 + g];
                dv = *(const float4*)&dfeat[(size_t)e * 64 + g];
            }
            float f0 = fmaf(sv.x, dv.x, sm->sWeoh[(g + 0) * 3 + t] + sm->sbeoh[g + 0]);
            float f1 = fmaf(sv.y, dv.y, sm->sWeoh[(g + 1) * 3 + t] + sm->sbeoh[g + 1]);
            float f2 = fmaf(sv.z, dv.z, sm->sWeoh[(g + 2) * 3 + t] + sm->sbeoh[g + 2]);
            float f3 = fmaf(sv.w, dv.w, sm->sWeoh[(g + 3) * 3 + t] + sm->sbeoh[g + 3]);
            uint32_t hi, lo;
            const int g2 = g >> 1;
            split_pair(f0, f1, hi, lo);
            sm->Ah[g2 * 132 + el] = hi;
            sm->Al[g2 * 132 + el] = lo;
            split_pair(f2, f3, hi, lo);
            sm->Ah[(g2 + 1) * 132 + el] = hi;
            sm->Al[(g2 + 1) * 132 + el] = lo;
        }
    }
    __syncthreads();

    const int lane = tid & 31;
    const int wid  = tid >> 5;
    const int wm   = (wid >> 2) * 64;
    const int wj   = (wid & 3) * 32;
    const int fr   = lane >> 2;
    const int fq   = lane & 3;

    float acc[4][4][4];
#pragma unroll
    for (int i = 0; i < 4; ++i)
#pragma unroll
        for (int j = 0; j < 4; ++j)
#pragma unroll
            for (int r = 0; r < 4; ++r) acc[i][j][r] = 0.f;

#pragma unroll
    for (int c8 = 0; c8 < 32; c8 += 8) {
        uint32_t bh[4][2], bl[4][2];
#pragma unroll
        for (int j = 0; j < 4; ++j) {
            const int col = wj + j * 8 + fr;
            bh[j][0] = sm->Bh[(c8 + fq) * 132 + col];
            bh[j][1] = sm->Bh[(c8 + fq + 4) * 132 + col];
            bl[j][0] = sm->Bl[(c8 + fq) * 132 + col];
            bl[j][1] = sm->Bl[(c8 + fq + 4) * 132 + col];
        }
#pragma unroll
        for (int i = 0; i < 4; ++i) {
            const int row = wm + i * 16 + fr;
            uint32_t ah[4] = { sm->Ah[(c8 + fq) * 132 + row],
                               sm->Ah[(c8 + fq) * 132 + row + 8],
                               sm->Ah[(c8 + fq + 4) * 132 + row],
                               sm->Ah[(c8 + fq + 4) * 132 + row + 8] };
            uint32_t al[4] = { sm->Al[(c8 + fq) * 132 + row],
                               sm->Al[(c8 + fq) * 132 + row + 8],
                               sm->Al[(c8 + fq + 4) * 132 + row],
                               sm->Al[(c8 + fq + 4) * 132 + row + 8] };
#pragma unroll
            for (int j = 0; j < 4; ++j) {
                mma16816(acc[i][j], ah, bh[j]);
                mma16816(acc[i][j], ah, bl[j]);
                mma16816(acc[i][j], al, bh[j]);
            }
        }
    }

    // epilogue A (fragment order): (edge_w + b_el) * h_src -> v2 reds
#pragma unroll
    for (int i = 0; i < 4; ++i) {
#pragma unroll
        for (int half = 0; half < 2; ++half) {
            const int le  = wm + i * 16 + fr + half * 8;
            const int dst = sm->sdst[le];
            if (dst < 0) continue;
            const float* hrow = &h_src[(size_t)(e0 + le) * 128];
            float* orow = &g_hsum[(size_t)dst * 256];
#pragma unroll
            for (int j = 0; j < 4; ++j) {
                const int c = wj + j * 8 + fq * 2;
                float2 h = *(const float2*)&hrow[c];
                float w0 = acc[i][j][half * 2 + 0] + sm->sbel[c];
                float w1 = acc[i][j][half * 2 + 1] + sm->sbel[c + 1];
                red2(&orow[c], w0 * h.x, w1 * h.y);
            }
        }
    }

    // epilogue B: embed + c_src -> v4 reds (coalesced)
    {
        const int tx = tid & 15;
        const int ty = tid >> 4;
#pragma unroll
        for (int i = 0; i < 8; ++i) {
            const int le  = ty * 8 + i;
            const int dst = sm->sdst[le];
            if (dst < 0) continue;
            const int e = e0 + le;
            float4 m0 = *(const float4*)&embed[(size_t)e * 128 + tx * 8];
            float4 m1 = *(const float4*)&embed[(size_t)e * 128 + tx * 8 + 4];
            float* b = &g_hsum[(size_t)dst * 256 + 128 + tx * 8];
            red4(b,     m0.x, m0.y, m0.z, m0.w);
            red4(b + 4, m1.x, m1.y, m1.z, m1.w);
            float4 c0 = *(const float4*)&c_src[(size_t)e * 128 + tx * 8];
            float4 c1 = *(const float4*)&c_src[(size_t)e * 128 + tx * 8 + 4];
            float* cs = &g_csum[(size_t)dst * 128 + tx * 8];
            red4(cs,     c0.x, c0.y, c0.z, c0.w);
            red4(cs + 4, c1.x, c1.y, c1.z, c1.w);
        }
    }
}

// ---------------------------------------------------------------------------
// Gate GEMM via mma.sync bf16 3-term split, double-buffered (R12-exact core):
//   g_gates[N,512](fp16) = act( h_sum[N,256] @ B[256,512] + bias )
// Fast-intrinsic activations in the epilogue.
// ---------------------------------------------------------------------------
__global__ __launch_bounds__(256) void k_mgemm(int N)
{
    __shared__ uint32_t Ah2[2][8][132];
    __shared__ uint32_t Al2[2][8][132];
    __shared__ uint32_t Bh2[2][8][132];
    __shared__ uint32_t Bl2[2][8][132];

    const int tid  = threadIdx.x;
    const int lane = tid & 31;
    const int wid  = tid >> 5;
    const int m0   = blockIdx.y * 128;
    const int j0   = blockIdx.x * 128;
    const int wm   = (wid >> 2) * 64;
    const int wj   = (wid & 3) * 32;

    float acc[4][4][4];
#pragma unroll
    for (int i = 0; i < 4; ++i)
#pragma unroll
        for (int j = 0; j < 4; ++j)
#pragma unroll
            for (int r = 0; r < 4; ++r) acc[i][j][r] = 0.f;

    const int  arow = tid >> 1;
    const int  akq  = tid & 1;
    const bool arok = (m0 + arow) < N;
    const int  bbr  = tid >> 5;
    const int  bjc  = (tid & 31) * 4;

    float4 pa0, pa1;
    uint4  pbh, pbl;

    auto prefetch = [&](int kc) {
        pa0 = make_float4(0.f, 0.f, 0.f, 0.f);
        pa1 = pa0;
        if (arok) {
            const float* src = &g_hsum[(size_t)(m0 + arow) * 256 + kc * 16 + akq * 8];
            pa0 = *(const float4*)(src);
            pa1 = *(const float4*)(src + 4);
        }
        pbh = *(const uint4*)&g_Bh2[(size_t)(kc * 8 + bbr) * 512 + j0 + bjc];
        pbl = *(const uint4*)&g_Bl2[(size_t)(kc * 8 + bbr) * 512 + j0 + bjc];
    };
    auto store_chunk = [&](int buf) {
        const int kb = akq * 4;
        split_pair(pa0.x, pa0.y, Ah2[buf][kb + 0][arow], Al2[buf][kb + 0][arow]);
        split_pair(pa0.z, pa0.w, Ah2[buf][kb + 1][arow], Al2[buf][kb + 1][arow]);
        split_pair(pa1.x, pa1.y, Ah2[buf][kb + 2][arow], Al2[buf][kb + 2][arow]);
        split_pair(pa1.z, pa1.w, Ah2[buf][kb + 3][arow], Al2[buf][kb + 3][arow]);
        *(uint4*)&Bh2[buf][bbr][bjc] = pbh;
        *(uint4*)&Bl2[buf][bbr][bjc] = pbl;
    };

    prefetch(0);
    store_chunk(0);
    __syncthreads();

    const int fr = lane >> 2;
    const int fk = lane & 3;

    for (int kc = 0; kc < 16; ++kc) {
        const int cur = kc & 1;
        if (kc < 15) prefetch(kc + 1);

        uint32_t bh[4][2], bl[4][2];
#pragma unroll
        for (int j = 0; j < 4; ++j) {
            const int col = wj + j * 8 + fr;
            bh[j][0] = Bh2[cur][fk][col];
            bh[j][1] = Bh2[cur][fk + 4][col];
            bl[j][0] = Bl2[cur][fk][col];
            bl[j][1] = Bl2[cur][fk + 4][col];
        }
#pragma unroll
        for (int i = 0; i < 4; ++i) {
            const int row = wm + i * 16 + fr;
            uint32_t ah[4] = { Ah2[cur][fk][row], Ah2[cur][fk][row + 8],
                               Ah2[cur][fk + 4][row], Ah2[cur][fk + 4][row + 8] };
            uint32_t al[4] = { Al2[cur][fk][row], Al2[cur][fk][row + 8],
                               Al2[cur][fk + 4][row], Al2[cur][fk + 4][row + 8] };
#pragma unroll
            for (int j = 0; j < 4; ++j) {
                mma16816(acc[i][j], ah, bh[j]);
                mma16816(acc[i][j], ah, bl[j]);
                mma16816(acc[i][j], al, bh[j]);
            }
        }

        if (kc < 15) store_chunk(cur ^ 1);
        __syncthreads();
    }

    const int q = blockIdx.x;   // gate: 0=f 1=i 2=u(tanh) 3=o
#pragma unroll
    for (int j = 0; j < 4; ++j) {
        const int c = j0 + wj + j * 8 + (lane & 3) * 2;
        const float b0 = g_bias[c], b1 = g_bias[c + 1];
#pragma unroll
        for (int i = 0; i < 4; ++i) {
            const int mr = m0 + wm + i * 16 + (lane >> 2);
#pragma unroll
            for (int half = 0; half < 2; ++half) {
                const int m = mr + half * 8;
                if (m >= N) continue;
                float v0 = acc[i][j][half * 2 + 0] + b0;
                float v1 = acc[i][j][half * 2 + 1] + b1;
                float o0, o1;
                if (q == 2) { o0 = tanh_fast(v0);    o1 = tanh_fast(v1); }
                else        { o0 = sigmoid_fast(v0); o1 = sigmoid_fast(v1); }
                *(__half2*)&g_gates[(size_t)m * 512 + c] = __floats2half2_rn(o0, o1);
            }
        }
    }
}

// ---------------------------------------------------------------------------
// Finalize: c = i*u + f*c_sum ; h = o*tanh(c) ; out = [h | c]
// ---------------------------------------------------------------------------
__global__ void k_final(float* __restrict__ out, int N)
{
    int id = blockIdx.x * blockDim.x + threadIdx.x;
    int n  = id >> 5;
    if (n >= N) return;
    int h4 = (id & 31) * 4;
    const __half* gr = &g_gates[(size_t)n * 512];

    uint2 uf = *(const uint2*)&gr[0   + h4];
    uint2 ui = *(const uint2*)&gr[128 + h4];
    uint2 uu = *(const uint2*)&gr[256 + h4];
    uint2 uo = *(const uint2*)&gr[384 + h4];
    float2 f01 = __half22float2(*(__half2*)&uf.x), f23 = __half22float2(*(__half2*)&uf.y);
    float2 i01 = __half22float2(*(__half2*)&ui.x), i23 = __half22float2(*(__half2*)&ui.y);
    float2 u01 = __half22float2(*(__half2*)&uu.x), u23 = __half22float2(*(__half2*)&uu.y);
    float2 o01 = __half22float2(*(__half2*)&uo.x), o23 = __half22float2(*(__half2*)&uo.y);

    float4 cs = *(const float4*)&g_csum[(size_t)n * 128 + h4];
    float4 c, h;
    c.x = fmaf(i01.x, u01.x, f01.x * cs.x);  h.x = o01.x * tanhf(c.x);
    c.y = fmaf(i01.y, u01.y, f01.y * cs.y);  h.y = o01.y * tanhf(c.y);
    c.z = fmaf(i23.x, u23.x, f23.x * cs.z);  h.z = o23.x * tanhf(c.z);
    c.w = fmaf(i23.y, u23.y, f23.y * cs.w);  h.w = o23.y * tanhf(c.w);
    *(float4*)&out[(size_t)n * 256 + h4]       = h;
    *(float4*)&out[(size_t)n * 256 + 128 + h4] = c;
}

// ---------------------------------------------------------------------------
// Launch
// ---------------------------------------------------------------------------
extern "C" void kernel_launch(void* const* d_in, const int* in_sizes, int n_in,
                              void* d_out, int out_size)
{
    const float* h_src = (const float*)d_in[0];
    const float* c_src = (const float*)d_in[1];
    const float* embed = (const float*)d_in[2];
    const float* sfeat = (const float*)d_in[3];
    const float* dfeat = (const float*)d_in[4];
    const float* Wf  = (const float*)d_in[5];
    const float* bWf = (const float*)d_in[6];
    const float* bf  = (const float*)d_in[7];
    const float* Wi  = (const float*)d_in[8];
    const float* bWi = (const float*)d_in[9];
    const float* bi  = (const float*)d_in[10];
    const float* Wu  = (const float*)d_in[11];
    const float* bWu = (const float*)d_in[12];
    const float* bu  = (const float*)d_in[13];
    const float* Wo  = (const float*)d_in[14];
    const float* bWo = (const float*)d_in[15];
    const float* bo  = (const float*)d_in[16];
    const float* W_eoh = (const float*)d_in[17];
    const float* b_eoh = (const float*)d_in[18];
    const float* W_el  = (const float*)d_in[19];
    const float* b_el  = (const float*)d_in[20];
    const void*  etype = d_in[21];
    const void*  dsti  = d_in[22];

    const int E = in_sizes[0] / 128;
    const int N = out_size   / 256;

    cudaFuncSetAttribute(k_edgemm, cudaFuncAttributeMaxDynamicSharedMemorySize,
                         (int)sizeof(EdgeSm));

    // 1) zero scatter targets via driver memsets
    void *p_hsum = nullptr, *p_csum = nullptr;
    cudaGetSymbolAddress(&p_hsum, g_hsum);
    cudaGetSymbolAddress(&p_csum, g_csum);
    cudaMemsetAsync(p_hsum, 0, (size_t)N * 256 * sizeof(float));
    cudaMemsetAsync(p_csum, 0, (size_t)N * 128 * sizeof(float));

    // 2) merged setup: weight/bias packing + index dtype probe
    k_setup<<<275, 256>>>(Wf, Wi, Wu, Wo, bWf, bf, bWi, bi, bWu, bu, bWo, bo,
                          W_el, (const unsigned int*)dsti);

    // 3) edge-message GEMM (tensor) + scatter h_sum / c_sum
    k_edgemm<<<(E + 127) / 128, 256, sizeof(EdgeSm)>>>(
        h_src, embed, c_src, sfeat, dfeat, W_eoh, b_eoh, b_el, etype, dsti, E);

    // 4) gate GEMM (mma.sync bf16 3-term, double-buffered) + fast activations
    dim3 gg(4, (N + 127) / 128);
    k_mgemm<<<gg, 256>>>(N);

    // 5) finalize:  c = i*u + f*c_sum ; h = o*tanh(c)
    k_final<<<(N * 32 + 255) / 256, 256>>>((float*)d_out, N);
}